// round 11
// baseline (speedup 1.0000x reference)
#include <cuda_runtime.h>
#include <cuda_fp16.h>
#include <math.h>

#define NMAX 100000
#define EMAX 1600000
#define FEAT 64

// Scratch (device globals — the sanctioned workaround for no-alloc rule)
__device__ float  g_dinv[NMAX];                        // rsqrt(deg)
__device__ int    g_count[NMAX];                       // histogram (zero-at-exit invariant)
__device__ int    g_start[NMAX + 1];                   // CSR offsets (+ sentinel at [n])
__device__ int    g_bsum[128];                         // scan block sums
__device__ int    g_slot[EMAX];                        // per-edge within-node rank
__device__ int    g_srcs[EMAX];                        // CSR: src ids grouped by dst
__device__ __align__(16) __half g_hs[NMAX * FEAT];     // (X@W)*dinv, fp16
__device__ __align__(16) float  g_act[NMAX * FEAT];    // layer-1 post-relu output

// ---------------------------------------------------------------------------
// CSR build pipeline  (g_count zero on entry: static init call 1, re-zeroed
// by k_scan3 every call)
// ---------------------------------------------------------------------------

// Histogram + slot capture, 4 edges/thread via int4 (e % 4 == 0 fast path)
__global__ void k_hist4(const int* __restrict__ ei, int e) {
    int i = blockIdx.x * blockDim.x + threadIdx.x;
    if (i * 4 < e) {
        int4 d = ((const int4*)(ei + e))[i];
        int4 sl;
        sl.x = atomicAdd(&g_count[d.x], 1);
        sl.y = atomicAdd(&g_count[d.y], 1);
        sl.z = atomicAdd(&g_count[d.z], 1);
        sl.w = atomicAdd(&g_count[d.w], 1);
        ((int4*)g_slot)[i] = sl;                     // coalesced
    }
}
__global__ void k_hist1(const int* __restrict__ ei, int e) {
    int i = blockIdx.x * blockDim.x + threadIdx.x;
    if (i < e) g_slot[i] = atomicAdd(&g_count[ei[e + i]], 1);
}

// Exclusive scan over g_count -> g_start (1024/block, shfl-based) + dinv fused
__global__ void k_scan1(int n) {
    __shared__ int wsum[32];
    int t = threadIdx.x;
    int i = blockIdx.x * 1024 + t;
    int v = (i < n) ? g_count[i] : 0;
    if (i < n) g_dinv[i] = rsqrtf((float)v + 1.0f);

    int lane = t & 31, w = t >> 5;
    int s = v;
#pragma unroll
    for (int off = 1; off < 32; off <<= 1) {
        int u = __shfl_up_sync(0xffffffff, s, off);
        if (lane >= off) s += u;
    }
    if (lane == 31) wsum[w] = s;
    __syncthreads();
    if (w == 0) {
        int ws = wsum[lane];
#pragma unroll
        for (int off = 1; off < 32; off <<= 1) {
            int u = __shfl_up_sync(0xffffffff, ws, off);
            if (lane >= off) ws += u;
        }
        wsum[lane] = ws;
    }
    __syncthreads();
    int excl = s - v + (w > 0 ? wsum[w - 1] : 0);
    if (i < n) g_start[i] = excl;
    if (t == 1023) g_bsum[blockIdx.x] = wsum[31];
}

// Finalize offsets (fused block-offset reduction over bsum),
// zero g_count (invariant), write sentinel g_start[n]=e.
__global__ void k_scan3(int n, int nb1, int e) {
    __shared__ int red[8];
    __shared__ int s_off;
    int t = threadIdx.x;
    int blk_of = blockIdx.x >> 2;                    // scan1 window index

    int v = (t < nb1 && t < blk_of) ? g_bsum[t] : 0;
    if (t < 128) {
        int lane = t & 31, w = t >> 5;
#pragma unroll
        for (int off = 16; off > 0; off >>= 1)
            v += __shfl_down_sync(0xffffffff, v, off);
        if (lane == 0) red[w] = v;
    }
    __syncthreads();
    if (t == 0) s_off = red[0] + red[1] + red[2] + red[3];
    __syncthreads();

    int i = blockIdx.x * 256 + t;
    if (i < n) {
        g_start[i] += s_off;
        g_count[i]  = 0;                             // restore invariant
    }
    if (i == 0) g_start[n] = e;
}

// Placement: NO atomics. pos = start[dst] + slot.
__global__ void k_place4(const int* __restrict__ ei, int e) {
    int i = blockIdx.x * blockDim.x + threadIdx.x;
    if (i * 4 < e) {
        int4 s  = ((const int4*)ei)[i];
        int4 d  = ((const int4*)(ei + e))[i];
        int4 sl = ((const int4*)g_slot)[i];
        g_srcs[g_start[d.x] + sl.x] = s.x;
        g_srcs[g_start[d.y] + sl.y] = s.y;
        g_srcs[g_start[d.z] + sl.z] = s.z;
        g_srcs[g_start[d.w] + sl.w] = s.w;
    }
}
__global__ void k_place1(const int* __restrict__ ei, int e) {
    int i = blockIdx.x * blockDim.x + threadIdx.x;
    if (i < e) g_srcs[g_start[ei[e + i]] + g_slot[i]] = ei[i];
}

// ---------------------------------------------------------------------------
// GEMM: HS = (X @ W) * dinv[row] -> fp16   (X: [n,64], W: [64,64])
// 256 threads, 128 rows/block, 8x4 micro-tile, k unrolled x4, float4 LDS
// ---------------------------------------------------------------------------
__global__ void __launch_bounds__(256) k_gemm64(
        const float* __restrict__ X, const float* __restrict__ W,
        int n, int use_act) {
    __shared__ float  sW[64 * 64];                   // 16 KB
    __shared__ float4 sX4[128 * 16];                 // 32 KB
    const float* Xp = use_act ? g_act : X;
    int t = threadIdx.x;
    int n0 = blockIdx.x * 128;

#pragma unroll
    for (int i = 0; i < 16; i++) sW[t + 256 * i] = W[t + 256 * i];
    const float4* Xg4 = (const float4*)Xp;
#pragma unroll
    for (int i = 0; i < 8; i++) {
        int idx = t + 256 * i;
        int r = idx >> 4, c = idx & 15;
        sX4[idx] = (n0 + r < n) ? Xg4[(size_t)(n0 + r) * 16 + c]
                                : make_float4(0.f, 0.f, 0.f, 0.f);
    }
    __syncthreads();

    int tx = t & 15, ty = t >> 4;
    float acc[8][4];
#pragma unroll
    for (int i = 0; i < 8; i++)
#pragma unroll
        for (int j = 0; j < 4; j++) acc[i][j] = 0.0f;

#pragma unroll
    for (int k4 = 0; k4 < 16; k4++) {
        float4 w0 = *(const float4*)&sW[(k4 * 4 + 0) * 64 + tx * 4];
        float4 w1 = *(const float4*)&sW[(k4 * 4 + 1) * 64 + tx * 4];
        float4 w2 = *(const float4*)&sW[(k4 * 4 + 2) * 64 + tx * 4];
        float4 w3 = *(const float4*)&sW[(k4 * 4 + 3) * 64 + tx * 4];
#pragma unroll
        for (int i = 0; i < 8; i++) {
            float4 xv = sX4[(ty * 8 + i) * 16 + k4];
            acc[i][0] = fmaf(xv.x, w0.x, acc[i][0]);
            acc[i][1] = fmaf(xv.x, w0.y, acc[i][1]);
            acc[i][2] = fmaf(xv.x, w0.z, acc[i][2]);
            acc[i][3] = fmaf(xv.x, w0.w, acc[i][3]);
            acc[i][0] = fmaf(xv.y, w1.x, acc[i][0]);
            acc[i][1] = fmaf(xv.y, w1.y, acc[i][1]);
            acc[i][2] = fmaf(xv.y, w1.z, acc[i][2]);
            acc[i][3] = fmaf(xv.y, w1.w, acc[i][3]);
            acc[i][0] = fmaf(xv.z, w2.x, acc[i][0]);
            acc[i][1] = fmaf(xv.z, w2.y, acc[i][1]);
            acc[i][2] = fmaf(xv.z, w2.z, acc[i][2]);
            acc[i][3] = fmaf(xv.z, w2.w, acc[i][3]);
            acc[i][0] = fmaf(xv.w, w3.x, acc[i][0]);
            acc[i][1] = fmaf(xv.w, w3.y, acc[i][1]);
            acc[i][2] = fmaf(xv.w, w3.z, acc[i][2]);
            acc[i][3] = fmaf(xv.w, w3.w, acc[i][3]);
        }
    }

#pragma unroll
    for (int i = 0; i < 8; i++) {
        int r = n0 + ty * 8 + i;
        if (r < n) {
            float di = g_dinv[r];
            __half2* dst = (__half2*)&g_hs[(size_t)r * 64 + tx * 4];
            dst[0] = __floats2half2_rn(acc[i][0] * di, acc[i][1] * di);
            dst[1] = __floats2half2_rn(acc[i][2] * di, acc[i][3] * di);
        }
    }
}

// ---------------------------------------------------------------------------
// Warp-level gather core:  returns relu(dinv[node]*(hs[node]+sum hs[src])+b)
// for this lane's 2 features. Full warp-per-node parallelism.
// ---------------------------------------------------------------------------
__device__ __forceinline__ float2 gather_node(int node, int lane, float2 bv) {
    int s0  = g_start[node];
    int deg = g_start[node + 1] - s0;
    const int* __restrict__ srcs = g_srcs + s0;
    const __half2* __restrict__ hs2 = (const __half2*)g_hs;

    float2 acc = __half22float2(hs2[(size_t)node * 32 + lane]); // self-loop

    int j = 0;
    int end8 = deg & ~7;
    for (; j < end8; j += 8) {
        int s[8];
#pragma unroll
        for (int q = 0; q < 8; q++) s[q] = srcs[j + q];
        __half2 v[8];
#pragma unroll
        for (int q = 0; q < 8; q++) v[q] = hs2[(size_t)s[q] * 32 + lane];
#pragma unroll
        for (int q = 0; q < 8; q++) {
            float2 f = __half22float2(v[q]);
            acc.x += f.x;
            acc.y += f.y;
        }
    }
    for (; j < deg; j++) {
        float2 f = __half22float2(hs2[(size_t)srcs[j] * 32 + lane]);
        acc.x += f.x;
        acc.y += f.y;
    }

    float di = g_dinv[node];
    float2 o;
    o.x = fmaxf(fmaf(acc.x, di, bv.x), 0.0f);
    o.y = fmaxf(fmaf(acc.y, di, bv.y), 0.0f);
    return o;
}

// Layer-1 gather: one warp per node, writes fp32 act to global
__global__ void k_gather(const float* __restrict__ bias, int n) {
    int warp = (blockIdx.x * blockDim.x + threadIdx.x) >> 5;
    if (warp >= n) return;
    int lane = threadIdx.x & 31;
    float2 bv = ((const float2*)bias)[lane];
    float2 o = gather_node(warp, lane, bv);
    ((float2*)g_act)[(size_t)warp * 32 + lane] = o;
}

// ---------------------------------------------------------------------------
// Fused layer-2 gather + FC head: 512 threads = 16 warps = 16 nodes.
// Warp gathers its node into smem (stride 68 to dodge bank conflicts),
// then 256 threads compute the 16x16 FC outputs straight to d_out.
// ---------------------------------------------------------------------------
__global__ void __launch_bounds__(512) k_gather_fc(
        const float* __restrict__ bias2, const float* __restrict__ Wfc,
        const float* __restrict__ bfc, float* __restrict__ out, int n) {
    __shared__ float sW[64 * 16];                    // 4 KB
    __shared__ float sB[16];
    __shared__ float sAct[16 * 68];                  // 4.25 KB, padded rows
    int t = threadIdx.x;

    sW[t] = Wfc[t];
    sW[t + 512] = Wfc[t + 512];
    if (t < 16) sB[t] = bfc[t];

    int n0 = blockIdx.x * 16;
    int w = t >> 5, lane = t & 31;
    int node = n0 + w;

    float2 o = make_float2(0.f, 0.f);
    if (node < n) {
        float2 bv = ((const float2*)bias2)[lane];
        o = gather_node(node, lane, bv);
    }
    *(float2*)&sAct[w * 68 + lane * 2] = o;
    __syncthreads();

    if (t < 256) {
        int j = t & 15, nl = t >> 4;                 // col, local node
        float acc = sB[j];
#pragma unroll
        for (int k = 0; k < 64; k++)
            acc = fmaf(sAct[nl * 68 + k], sW[k * 16 + j], acc);
        int r = n0 + nl;
        if (r < n) out[(size_t)r * 16 + j] = acc;
    }
}

// ---------------------------------------------------------------------------
extern "C" void kernel_launch(void* const* d_in, const int* in_sizes, int n_in,
                              void* d_out, int out_size) {
    const float* x   = (const float*)d_in[0];
    const int*   ei  = (const int*)d_in[1];   // int32 (JAX x64 disabled)
    const float* W1  = (const float*)d_in[2];
    const float* b1  = (const float*)d_in[3];
    const float* W2  = (const float*)d_in[4];
    const float* b2  = (const float*)d_in[5];
    const float* Wfc = (const float*)d_in[6];
    const float* bfc = (const float*)d_in[7];
    float* out = (float*)d_out;

    int n = in_sizes[0] / FEAT;
    int e = in_sizes[1] / 2;

    int nb_n   = (n + 255) / 256;
    int nb_e4  = (int)(((long long)e / 4 + 255) / 256);
    int nb_e   = (e + 255) / 256;
    int nb_g   = (n + 127) / 128;
    int nb_s1  = (n + 1023) / 1024;
    int nb_ga  = (int)(((long long)n * 32 + 255) / 256);
    int nb_gfc = (n + 15) / 16;

    // CSR build (counts zero on entry — invariant restored by k_scan3)
    if ((e & 3) == 0) k_hist4<<<nb_e4, 256>>>(ei, e);
    else              k_hist1<<<nb_e, 256>>>(ei, e);
    k_scan1<<<nb_s1, 1024>>>(n);
    k_scan3<<<nb_n, 256>>>(n, nb_s1, e);
    if ((e & 3) == 0) k_place4<<<nb_e4, 256>>>(ei, e);
    else              k_place1<<<nb_e, 256>>>(ei, e);

    // Layer 1
    k_gemm64<<<nb_g, 256>>>(x, W1, n, 0);
    k_gather<<<nb_ga, 256>>>(b1, n);

    // Layer 2 GEMM + fused gather+FC
    k_gemm64<<<nb_g, 256>>>(x, W2, n, 1);
    k_gather_fc<<<nb_gfc, 512>>>(b2, Wfc, bfc, out, n);
}